// round 16
// baseline (speedup 1.0000x reference)
#include <cuda_runtime.h>

// PlasticLinearRec: B=128, F=512
//   M[b,j,k]   = weight[j,k] + plastic_scale[j,k] * hebb[b,j,k]
//   pre[b,j]   = sum_k last_out[b,k] * M[b,j,k]
//   out[b,j]   = tanh(pre[b,j] + input[b,j])
//   hebb_new[b,j,k] = hebb[b,j,k] + lr * out[b,j] * (last_out[b,k] - out[b,j]*hebb[b,j,k])
//
// Fully fused single pass: one warp owns one (b,j) row of hebb (512 floats,
// held in registers as 4x float4 per lane), reduces the dot product via
// shuffles, then rewrites the row. Warp index wg = j*128 + b so the 8 warps
// in a block share j => weight/scale rows are L1-resident after first warp.

#define FDIM 512
#define BDIM 128
#define F4   (FDIM / 4)   // 128 float4 per row

__global__ __launch_bounds__(256, 8)
void plastic_linear_rec_kernel(
    const float*  __restrict__ input,      // [B,F]
    const float*  __restrict__ last_out,   // [B,F]
    const float4* __restrict__ hebb,       // [B,F,F] as float4
    const float4* __restrict__ weight,     // [F,F]  as float4
    const float4* __restrict__ scale,      // [F,F]  as float4
    const float*  __restrict__ lr_ptr,     // [1]
    float*        __restrict__ out,        // [B,F]
    float4*       __restrict__ hebb_new)   // [B,F,F] as float4
{
    const int wg   = (blockIdx.x * blockDim.x + threadIdx.x) >> 5;  // 0..65535
    const int lane = threadIdx.x & 31;
    const int j = wg >> 7;          // 0..511  (shared within a block of 8 warps)
    const int b = wg & 127;         // 0..127

    const size_t row = (size_t)b * FDIM + j;            // (b,j) row id
    const float4* __restrict__ hrow = hebb   + row * F4;
    const float4* __restrict__ wrow = weight + (size_t)j * F4;
    const float4* __restrict__ srow = scale  + (size_t)j * F4;
    const float4* __restrict__ lrow = reinterpret_cast<const float4*>(last_out)
                                      + (size_t)b * F4;

    float4 h[4], l[4];
    float sum = 0.0f;
#pragma unroll
    for (int i = 0; i < 4; i++) {
        const int idx = lane + 32 * i;
        const float4 hv = __ldg(hrow + idx);
        const float4 lv = __ldg(lrow + idx);
        const float4 wv = __ldg(wrow + idx);
        const float4 sv = __ldg(srow + idx);
        h[i] = hv;
        l[i] = lv;
        sum += lv.x * fmaf(sv.x, hv.x, wv.x);
        sum += lv.y * fmaf(sv.y, hv.y, wv.y);
        sum += lv.z * fmaf(sv.z, hv.z, wv.z);
        sum += lv.w * fmaf(sv.w, hv.w, wv.w);
    }

    // warp-wide reduction (full warp, every lane gets the sum)
#pragma unroll
    for (int off = 16; off > 0; off >>= 1)
        sum += __shfl_xor_sync(0xffffffffu, sum, off);

    const float o  = tanhf(sum + __ldg(input + row));
    const float lr = __ldg(lr_ptr);
    if (lane == 0)
        out[row] = o;

    float4* __restrict__ hn = hebb_new + row * F4;
    const float lo = lr * o;
#pragma unroll
    for (int i = 0; i < 4; i++) {
        const int idx = lane + 32 * i;
        float4 r;
        r.x = fmaf(lo, fmaf(-o, h[i].x, l[i].x), h[i].x);
        r.y = fmaf(lo, fmaf(-o, h[i].y, l[i].y), h[i].y);
        r.z = fmaf(lo, fmaf(-o, h[i].z, l[i].z), h[i].z);
        r.w = fmaf(lo, fmaf(-o, h[i].w, l[i].w), h[i].w);
        hn[idx] = r;
    }
}

extern "C" void kernel_launch(void* const* d_in, const int* in_sizes, int n_in,
                              void* d_out, int out_size)
{
    // metadata order: input, last_out, hebb, weight, plastic_scale, plastic_lr
    const float*  input    = (const float*) d_in[0];   // 128*512
    const float*  last_out = (const float*) d_in[1];   // 128*512
    const float4* hebb     = (const float4*)d_in[2];   // 128*512*512
    const float4* weight   = (const float4*)d_in[3];   // 512*512
    const float4* scale    = (const float4*)d_in[4];   // 512*512
    const float*  lr       = (const float*) d_in[5];   // 1

    // outputs flattened in reference-return order: out [B,F], then hebb_new [B,F,F]
    float*  out      = (float*)d_out;
    float4* hebb_new = (float4*)((float*)d_out + (size_t)BDIM * FDIM);

    // one warp per (b,j) row: 128*512 = 65536 warps
    const int threads = 256;                          // 8 warps / block
    const int blocks  = (BDIM * FDIM * 32) / threads; // 8192

    plastic_linear_rec_kernel<<<blocks, threads>>>(
        input, last_out, hebb, weight, scale, lr, out, hebb_new);
}

// round 17
// speedup vs baseline: 1.6542x; 1.6542x over previous
#include <cuda_runtime.h>

// PlasticLinearRec: B=128, F=512
//   pre[b,j]   = sum_k last_out[b,k] * (weight[j,k] + scale[j,k]*hebb[b,j,k])
//   out[b,j]   = tanh(pre[b,j] + input[b,j])
//   hebb_new[b,j,k] = hebb + lr*out[b,j]*(last_out[b,k] - out[b,j]*hebb)
//
// R16: warp owns one j and loops over 8 batches, holding weight/scale rows in
// registers (amortizes the w/s stream 8x). Block = 8 warps sharing a batch
// chunk with consecutive j -> last_out rows L1-shared. hebb uses streaming
// cache hints (__ldcs/__stcs) so the 256MB stream doesn't evict the resident
// w/s/last_out sets from L2. Batch loop is software-pipelined: next row's
// h/l loads are issued before the current row's shuffle-reduce + tanh chain.

#define FDIM 512
#define BDIM 128
#define F4   (FDIM / 4)   // 128 float4 per row
#define BT   8            // batches per warp

__device__ __forceinline__ float dot16(const float4* h, const float4* l,
                                       const float4* w, const float4* s)
{
    float sum = 0.0f;
#pragma unroll
    for (int i = 0; i < 4; i++) {
        sum += l[i].x * fmaf(s[i].x, h[i].x, w[i].x);
        sum += l[i].y * fmaf(s[i].y, h[i].y, w[i].y);
        sum += l[i].z * fmaf(s[i].z, h[i].z, w[i].z);
        sum += l[i].w * fmaf(s[i].w, h[i].w, w[i].w);
    }
    return sum;
}

__global__ __launch_bounds__(256, 2)
void plastic_linear_rec_kernel(
    const float*  __restrict__ input,      // [B,F]
    const float4* __restrict__ last_out,   // [B,F]   as float4
    const float4* __restrict__ hebb,       // [B,F,F] as float4
    const float4* __restrict__ weight,     // [F,F]   as float4
    const float4* __restrict__ scale,      // [F,F]   as float4
    const float*  __restrict__ lr_ptr,     // [1]
    float*        __restrict__ out,        // [B,F]
    float4*       __restrict__ hebb_new)   // [B,F,F] as float4
{
    const int warp = threadIdx.x >> 5;       // 0..7
    const int lane = threadIdx.x & 31;
    const int jgrp  = blockIdx.x >> 4;       // 0..63 (8 j's per block)
    const int chunk = blockIdx.x & 15;       // 0..15 (8 batches per chunk)
    const int j  = jgrp * 8 + warp;          // 0..511
    const int b0 = chunk * BT;               // 0..120

    const float lr = __ldg(lr_ptr);

    // weight/scale rows for this j: held in registers for all BT batches
    const float4* __restrict__ wrow = weight + (size_t)j * F4;
    const float4* __restrict__ srow = scale  + (size_t)j * F4;
    float4 w[4], s[4];
#pragma unroll
    for (int i = 0; i < 4; i++) {
        w[i] = __ldg(wrow + lane + 32 * i);
        s[i] = __ldg(srow + lane + 32 * i);
    }

    // prologue: load batch b0's hebb row (streaming) + last_out row
    size_t row = (size_t)b0 * FDIM + j;
    float4 h[4], l[4];
#pragma unroll
    for (int i = 0; i < 4; i++) {
        h[i] = __ldcs(hebb + row * F4 + lane + 32 * i);
        l[i] = __ldg(last_out + (size_t)b0 * F4 + lane + 32 * i);
    }
    float in_cur = __ldg(input + row);

#pragma unroll
    for (int bb = 0; bb < BT; bb++) {
        const size_t cur_row = row;

        // prefetch next batch's rows before the serial reduce/tanh chain
        float4 hn[4], ln[4];
        float in_next = 0.0f;
        if (bb < BT - 1) {
            const int bnext = b0 + bb + 1;
            const size_t nrow = (size_t)bnext * FDIM + j;
#pragma unroll
            for (int i = 0; i < 4; i++) {
                hn[i] = __ldcs(hebb + nrow * F4 + lane + 32 * i);
                ln[i] = __ldg(last_out + (size_t)bnext * F4 + lane + 32 * i);
            }
            in_next = __ldg(input + nrow);
            row = nrow;
        }

        // dot product + warp reduction (all lanes end with the sum)
        float sum = dot16(h, l, w, s);
#pragma unroll
        for (int off = 16; off > 0; off >>= 1)
            sum += __shfl_xor_sync(0xffffffffu, sum, off);

        const float o = tanhf(sum + in_cur);
        if (lane == 0)
            out[cur_row] = o;

        // hebb update + streaming store
        const float lo = lr * o;
        float4* __restrict__ hnw = hebb_new + cur_row * F4;
#pragma unroll
        for (int i = 0; i < 4; i++) {
            float4 r;
            r.x = fmaf(lo, fmaf(-o, h[i].x, l[i].x), h[i].x);
            r.y = fmaf(lo, fmaf(-o, h[i].y, l[i].y), h[i].y);
            r.z = fmaf(lo, fmaf(-o, h[i].z, l[i].z), h[i].z);
            r.w = fmaf(lo, fmaf(-o, h[i].w, l[i].w), h[i].w);
            __stcs(hnw + lane + 32 * i, r);
        }

        // rotate double buffers (renamed away by full unroll)
        if (bb < BT - 1) {
#pragma unroll
            for (int i = 0; i < 4; i++) { h[i] = hn[i]; l[i] = ln[i]; }
            in_cur = in_next;
        }
    }
}

extern "C" void kernel_launch(void* const* d_in, const int* in_sizes, int n_in,
                              void* d_out, int out_size)
{
    // metadata order: input, last_out, hebb, weight, plastic_scale, plastic_lr
    const float*  input    = (const float*) d_in[0];   // 128*512
    const float4* last_out = (const float4*)d_in[1];   // 128*512
    const float4* hebb     = (const float4*)d_in[2];   // 128*512*512
    const float4* weight   = (const float4*)d_in[3];   // 512*512
    const float4* scale    = (const float4*)d_in[4];   // 512*512
    const float*  lr       = (const float*) d_in[5];   // 1

    // outputs flattened in reference-return order: out [B,F], then hebb_new [B,F,F]
    float*  out      = (float*)d_out;
    float4* hebb_new = (float4*)((float*)d_out + (size_t)BDIM * FDIM);

    // 512 j * 16 batch-chunks = 8192 warps; 8 warps/block -> 1024 blocks
    plastic_linear_rec_kernel<<<1024, 256>>>(
        input, last_out, hebb, weight, scale, lr, out, hebb_new);
}